// round 1
// baseline (speedup 1.0000x reference)
#include <cuda_runtime.h>
#include <math.h>

#define HIDDEN 2048
#define BOT    64
#define NEXP   8

#define BM 64
#define BK 64
#define THREADS 256
#define NTOK 16384

// Scratch (device globals: no allocations allowed)
__device__ float g_Gt[HIDDEN * BOT];   // Gt[k][d] = gamma[k] * w_down[d][k]
__device__ float g_s[BOT];             // s[d] = sum_k gamma[k] * w_down[d][k]
__device__ float g_t[BOT];             // t[d] = sum_k beta[k]  * w_down[d][k]

// ---------------- prep: build Gt, s, t (one block per expert-bottleneck dim) ----
__global__ void prep_kernel(const float* __restrict__ w_down,
                            const float* __restrict__ gamma,
                            const float* __restrict__ beta)
{
    __shared__ float red_s[8], red_t[8];
    const int d   = blockIdx.x;           // 0..63
    const int tid = threadIdx.x;          // 256
    float ps = 0.f, pt = 0.f;
    for (int k = tid; k < HIDDEN; k += THREADS) {
        float wd = w_down[d * HIDDEN + k];
        float gw = gamma[k] * wd;
        g_Gt[k * BOT + d] = gw;
        ps += gw;
        pt += beta[k] * wd;
    }
    #pragma unroll
    for (int o = 16; o > 0; o >>= 1) {
        ps += __shfl_xor_sync(0xffffffffu, ps, o);
        pt += __shfl_xor_sync(0xffffffffu, pt, o);
    }
    int w = tid >> 5, lane = tid & 31;
    if (lane == 0) { red_s[w] = ps; red_t[w] = pt; }
    __syncthreads();
    if (tid == 0) {
        float ss = 0.f, tt = 0.f;
        #pragma unroll
        for (int i = 0; i < 8; i++) { ss += red_s[i]; tt += red_t[i]; }
        g_s[d] = ss; g_t[d] = tt;
    }
}

// ---------------- f32x2 packed-FMA helpers (FFMA2: full-rate fp32 on sm_103a) ---
typedef unsigned long long u64;

__device__ __forceinline__ u64 dup2(float a) {
    u64 r;
    asm("mov.b64 %0, {%1, %1};" : "=l"(r) : "f"(a));
    return r;
}
__device__ __forceinline__ void fma2(u64& d, u64 a, u64 b) {
    asm("fma.rn.f32x2 %0, %1, %2, %0;" : "+l"(d) : "l"(a), "l"(b));
}
__device__ __forceinline__ void unpack2(u64 v, float& lo, float& hi) {
    asm("mov.b64 {%0, %1}, %2;" : "=f"(lo), "=f"(hi) : "l"(v));
}

// ---------------- main fused kernel -------------------------------------------
__global__ __launch_bounds__(THREADS) void router_kernel(
    const float* __restrict__ H,      // [16384][2048] raw hidden states
    const float* __restrict__ w_up,   // [8][64]
    float* __restrict__ out)          // [16384][8]
{
    __shared__ float As[BM * BK];     // [m][k], 16 KB; reused for z[m][d] after loop
    __shared__ float Bs[BK * BOT];    // [k][n], 16 KB; reused for mu/rstd/s/t/logits

    const int tid = threadIdx.x;
    const int g   = tid >> 4;         // 0..15 (row group / thread-row)
    const int c   = tid & 15;         // 0..15 (col group / thread-col)
    const int m0t = g * 4;            // thread's 4 output rows
    const int n0t = c * 4;            // thread's 4 output cols

    const float* Ag = H + (size_t)blockIdx.x * BM * HIDDEN;

    u64 acc[4][2];                    // acc[q][p] = f32x2 pair (n0t+2p, n0t+2p+1)
    #pragma unroll
    for (int q = 0; q < 4; q++) { acc[q][0] = 0ull; acc[q][1] = 0ull; }

    float psum[4] = {0.f, 0.f, 0.f, 0.f};   // LN stats for rows g+16p
    float psq[4]  = {0.f, 0.f, 0.f, 0.f};

    for (int kc = 0; kc < HIDDEN; kc += BK) {
        __syncthreads();
        // Load A tile (coalesced float4 along k) + accumulate LN stats
        #pragma unroll
        for (int p = 0; p < 4; p++) {
            int row = g + 16 * p;
            float4 v = *(const float4*)(Ag + (size_t)row * HIDDEN + kc + n0t);
            *(float4*)&As[row * BK + n0t] = v;
            psum[p] += v.x + v.y + v.z + v.w;
            psq[p]  += v.x * v.x + v.y * v.y + v.z * v.z + v.w * v.w;
        }
        // Load B tile (Gt already k-major: direct coalesced copy, no transpose)
        #pragma unroll
        for (int p = 0; p < 4; p++) {
            int k = g + 16 * p;
            *(float4*)&Bs[k * BOT + n0t] = *(const float4*)&g_Gt[(kc + k) * BOT + n0t];
        }
        __syncthreads();
        #pragma unroll
        for (int k4 = 0; k4 < BK / 4; k4++) {
            float4 av[4];
            #pragma unroll
            for (int q = 0; q < 4; q++)
                av[q] = *(const float4*)&As[(m0t + q) * BK + k4 * 4];
            #pragma unroll
            for (int j = 0; j < 4; j++) {
                // B n-pairs come pre-packed for f32x2 from a single LDS.128
                ulonglong2 b = *(const ulonglong2*)&Bs[(k4 * 4 + j) * BOT + n0t];
                #pragma unroll
                for (int q = 0; q < 4; q++) {
                    float a = (j == 0) ? av[q].x : (j == 1) ? av[q].y
                            : (j == 2) ? av[q].z : av[q].w;
                    u64 ad = dup2(a);
                    fma2(acc[q][0], ad, b.x);
                    fma2(acc[q][1], ad, b.y);
                }
            }
        }
    }
    __syncthreads();

    // LN stats: rows of group g live in lanes 16g..16g+15 -> half-warp shuffle reduce
    #pragma unroll
    for (int o = 1; o < 16; o <<= 1) {
        #pragma unroll
        for (int p = 0; p < 4; p++) {
            psum[p] += __shfl_xor_sync(0xffffffffu, psum[p], o);
            psq[p]  += __shfl_xor_sync(0xffffffffu, psq[p], o);
        }
    }
    if (c == 0) {
        #pragma unroll
        for (int p = 0; p < 4; p++) {
            int row = g + 16 * p;
            float mu  = psum[p] * (1.f / HIDDEN);
            float var = psq[p] * (1.f / HIDDEN) - mu * mu;
            Bs[row]      = mu;
            Bs[BM + row] = rsqrtf(var + 1e-5f);
        }
    }
    if (tid < BOT) {
        Bs[128 + tid] = g_s[tid];
        Bs[192 + tid] = g_t[tid];
    }
    __syncthreads();

    // Epilogue: z = silu(rstd*(dot - mu*s_n) + t_n) into As (reused as z[m][64])
    #pragma unroll
    for (int q = 0; q < 4; q++) {
        int m = m0t + q;
        float mu = Bs[m], rs = Bs[BM + m];
        float d0, d1, d2, d3;
        unpack2(acc[q][0], d0, d1);
        unpack2(acc[q][1], d2, d3);
        float dv[4] = {d0, d1, d2, d3};
        #pragma unroll
        for (int i = 0; i < 4; i++) {
            int n = n0t + i;
            float pre = rs * (dv[i] - mu * Bs[128 + n]) + Bs[192 + n];
            As[m * BOT + n] = pre / (1.f + expf(-pre));
        }
    }
    __syncthreads();

    // logits[m][e] = z[m] . w_up[e]   (512 dots of length 64; 2 per thread)
    #pragma unroll
    for (int p = 0; p < 2; p++) {
        int idx = tid + THREADS * p;
        int m = idx >> 3, e = idx & 7;
        float a = 0.f;
        #pragma unroll 8
        for (int d = 0; d < BOT; d++)
            a += As[m * BOT + d] * __ldg(&w_up[e * BOT + d]);
        Bs[256 + m * 8 + e] = a;
    }
    __syncthreads();

    // Top-2 softmax per token (first-index tie-break matches jax.lax.top_k)
    if (tid < BM) {
        int m = tid;
        float l[8];
        #pragma unroll
        for (int e = 0; e < 8; e++) l[e] = Bs[256 + m * 8 + e];
        int i1 = 0; float m1 = l[0];
        #pragma unroll
        for (int e = 1; e < 8; e++) if (l[e] > m1) { m1 = l[e]; i1 = e; }
        int i2 = -1; float m2 = -3.4e38f;
        #pragma unroll
        for (int e = 0; e < 8; e++) if (e != i1 && l[e] > m2) { m2 = l[e]; i2 = e; }
        float p1 = 1.f / (1.f + expf(m2 - m1));   // m1 >= m2: stable
        float p2 = 1.f - p1;
        float* o = out + ((size_t)blockIdx.x * BM + m) * NEXP;
        #pragma unroll
        for (int e = 0; e < 8; e++)
            o[e] = (e == i1) ? p1 : (e == i2) ? p2 : 0.f;
    }
}

// ---------------- launch -------------------------------------------------------
extern "C" void kernel_launch(void* const* d_in, const int* in_sizes, int n_in,
                              void* d_out, int out_size)
{
    (void)in_sizes; (void)n_in; (void)out_size;
    const float* hs     = (const float*)d_in[0];  // (4,4096,2048) f32
    const float* w_down = (const float*)d_in[1];  // (64,2048) f32
    const float* w_up   = (const float*)d_in[2];  // (8,64) f32
    const float* gamma  = (const float*)d_in[3];  // (2048,) f32
    const float* beta   = (const float*)d_in[4];  // (2048,) f32
    float* out = (float*)d_out;                   // (4,4096,8) f32

    prep_kernel<<<BOT, THREADS>>>(w_down, gamma, beta);
    router_kernel<<<NTOK / BM, THREADS>>>(hs, w_up, out);
}

// round 3
// speedup vs baseline: 2.3267x; 2.3267x over previous
#include <cuda_runtime.h>
#include <cuda_bf16.h>
#include <math.h>
#include <stdint.h>

#define HIDDEN 2048
#define BOT    64
#define NEXP   8
#define NTOK   16384

#define BM       128
#define BK       64
#define NTILES   (HIDDEN / BK)       // 32
#define THREADS  256

// ---------------- dynamic smem layout (byte offsets) ---------------------------
#define A_HI(b)   ((b) * 16384)               // 2 x 16KB (128 rows x 128B bf16)
#define A_LO(b)   (32768 + (b) * 16384)       // 2 x 16KB
#define B_HI(b)   (65536 + (b) * 8192)        // 2 x 8KB  (64 rows x 128B bf16)
#define B_LO(b)   (81920 + (b) * 8192)        // 2 x 8KB
#define O_MU      98304                       // 128 f32
#define O_RS      98816                       // 128 f32
#define O_S       99328                       // 64 f32
#define O_T       99584                       // 64 f32
#define O_WUPT    99840                       // 512 f32: wupT[d][e]
#define SMEM_TOTAL 101888
#define ZSTRIDE   68                          // padded z row stride (f32)

#define SWZ128(off) ((off) ^ (((off) >> 3) & 0x70))

// ---------------- device scratch (no allocations allowed) ----------------------
__device__ uint4 g_Bhi4[NTILES * 512];   // 256KB pre-swizzled bf16 hi tiles [n][k]
__device__ uint4 g_Blo4[NTILES * 512];   // 256KB lo tiles
__device__ float g_s[BOT];
__device__ float g_t[BOT];

// ---------------- PTX helpers ---------------------------------------------------
__device__ __forceinline__ uint32_t smem_u32(const void* p) {
    uint32_t a;
    asm("{ .reg .u64 t; cvta.to.shared.u64 t, %1; cvt.u32.u64 %0, t; }" : "=r"(a) : "l"(p));
    return a;
}
#define LDMX4(r, a) \
    asm volatile("ldmatrix.sync.aligned.m8n8.x4.shared.b16 {%0,%1,%2,%3}, [%4];" \
        : "=r"((r)[0]), "=r"((r)[1]), "=r"((r)[2]), "=r"((r)[3]) : "r"(a))

#define MMA16816(d, a, b0, b1) \
    asm volatile("mma.sync.aligned.m16n8k16.row.col.f32.bf16.bf16.f32 " \
        "{%0,%1,%2,%3}, {%4,%5,%6,%7}, {%8,%9}, {%0,%1,%2,%3};" \
        : "+f"((d)[0]), "+f"((d)[1]), "+f"((d)[2]), "+f"((d)[3]) \
        : "r"((a)[0]), "r"((a)[1]), "r"((a)[2]), "r"((a)[3]), "r"(b0), "r"(b1))

// ---------------- prep: split G = gamma*W into bf16 hi/lo, pre-swizzled ---------
__global__ void prep_kernel(const float* __restrict__ w_down,
                            const float* __restrict__ gamma,
                            const float* __restrict__ beta)
{
    __shared__ float red_s[8], red_t[8];
    const int n   = blockIdx.x;           // 0..63 (bottleneck dim = B row)
    const int tid = threadIdx.x;          // 256
    __nv_bfloat16* bhi = (__nv_bfloat16*)g_Bhi4;
    __nv_bfloat16* blo = (__nv_bfloat16*)g_Blo4;
    float ps = 0.f, pt = 0.f;
    for (int k = tid; k < HIDDEN; k += 256) {
        float w = w_down[n * HIDDEN + k];
        float g = gamma[k] * w;
        __nv_bfloat16 h = __float2bfloat16_rn(g);
        float res = g - __bfloat162float(h);
        __nv_bfloat16 l = __float2bfloat16_rn(res);
        int tile = k >> 6, kk = k & 63;
        uint32_t off = (uint32_t)(n * 128 + kk * 2);
        uint32_t idx = (uint32_t)tile * 4096u + (SWZ128(off) >> 1);
        bhi[idx] = h;
        blo[idx] = l;
        ps += g;
        pt += beta[k] * w;
    }
    #pragma unroll
    for (int o = 16; o > 0; o >>= 1) {
        ps += __shfl_xor_sync(0xffffffffu, ps, o);
        pt += __shfl_xor_sync(0xffffffffu, pt, o);
    }
    int w = tid >> 5, lane = tid & 31;
    if (lane == 0) { red_s[w] = ps; red_t[w] = pt; }
    __syncthreads();
    if (tid == 0) {
        float ss = 0.f, tt = 0.f;
        #pragma unroll
        for (int i = 0; i < 8; i++) { ss += red_s[i]; tt += red_t[i]; }
        g_s[n] = ss; g_t[n] = tt;
    }
}

// ---------------- main fused HMMA kernel ----------------------------------------
extern __shared__ char dsm[];

__global__ __launch_bounds__(THREADS, 1)
void router_kernel(const float* __restrict__ H,      // [16384][2048]
                   const float* __restrict__ w_up,   // [8][64]
                   float* __restrict__ out)          // [16384][8]
{
    const uint32_t sb  = smem_u32(dsm);
    const int tid  = threadIdx.x;
    const int wid  = tid >> 5;
    const int lane = tid & 31;
    const int wm   = wid & 3;             // warp row-tile: rows wm*32..+32
    const int wn   = wid >> 2;            // warp col-tile: cols wn*32..+32

    // small tables
    {
        int i0 = tid, i1 = tid + 256;
        ((float*)(dsm + O_WUPT))[(i0 & 63) * 8 + (i0 >> 6)] = w_up[i0];
        ((float*)(dsm + O_WUPT))[(i1 & 63) * 8 + (i1 >> 6)] = w_up[i1];
        if (tid < BOT) {
            ((float*)(dsm + O_S))[tid] = g_s[tid];
            ((float*)(dsm + O_T))[tid] = g_t[tid];
        }
    }

    // per-thread A load geometry: coalesced float4; linear = (j*256+tid)*4
    // row = j*16 + tid/16,  k = (tid&15)*4
    const int lrow = tid >> 4;            // 0..15
    const int lk   = (tid & 15) * 4;      // 0..60
    const float* Hbase = H + ((size_t)blockIdx.x * BM + lrow) * HIDDEN + lk;
    const uint32_t sts_sw = SWZ128((uint32_t)(lrow * 128 + (tid & 15) * 8)); // row term added per j

    float acc[2][4][4];
    #pragma unroll
    for (int mi = 0; mi < 2; mi++)
        #pragma unroll
        for (int ni = 0; ni < 4; ni++)
            #pragma unroll
            for (int r = 0; r < 4; r++) acc[mi][ni][r] = 0.f;

    float psum[8], psq[8];
    #pragma unroll
    for (int j = 0; j < 8; j++) { psum[j] = 0.f; psq[j] = 0.f; }

    float4 pf[8];
    uint4  pb[4];

    // prologue: load + convert tile 0 into buf 0
    #pragma unroll
    for (int j = 0; j < 8; j++)
        pf[j] = *(const float4*)(Hbase + (size_t)j * 16 * HIDDEN);
    pb[0] = g_Bhi4[tid];        pb[1] = g_Bhi4[256 + tid];
    pb[2] = g_Blo4[tid];        pb[3] = g_Blo4[256 + tid];

    #pragma unroll 1
    for (int t = 0; t < NTILES; t++) {
        const int buf = t & 1;
        // ---- convert prefetched regs -> smem buf ----
        #pragma unroll
        for (int j = 0; j < 8; j++) {
            float4 v = pf[j];
            psum[j] += (v.x + v.y) + (v.z + v.w);
            psq[j]  = fmaf(v.x, v.x, psq[j]); psq[j] = fmaf(v.y, v.y, psq[j]);
            psq[j]  = fmaf(v.z, v.z, psq[j]); psq[j] = fmaf(v.w, v.w, psq[j]);
            __nv_bfloat162 h01 = __floats2bfloat162_rn(v.x, v.y);
            __nv_bfloat162 h23 = __floats2bfloat162_rn(v.z, v.w);
            float rx = v.x - __bfloat162float(h01.x);
            float ry = v.y - __bfloat162float(h01.y);
            float rz = v.z - __bfloat162float(h23.x);
            float rw = v.w - __bfloat162float(h23.y);
            __nv_bfloat162 l01 = __floats2bfloat162_rn(rx, ry);
            __nv_bfloat162 l23 = __floats2bfloat162_rn(rz, rw);
            uint32_t sw = sts_sw + (uint32_t)(j * 16 * 128);   // j*16 rows: swizzle bits unaffected (bits>=11)
            *(uint2*)(dsm + A_HI(buf) + sw) = make_uint2(*(uint32_t*)&h01, *(uint32_t*)&h23);
            *(uint2*)(dsm + A_LO(buf) + sw) = make_uint2(*(uint32_t*)&l01, *(uint32_t*)&l23);
        }
        *(uint4*)(dsm + B_HI(buf) + tid * 16)         = pb[0];
        *(uint4*)(dsm + B_HI(buf) + (256 + tid) * 16) = pb[1];
        *(uint4*)(dsm + B_LO(buf) + tid * 16)         = pb[2];
        *(uint4*)(dsm + B_LO(buf) + (256 + tid) * 16) = pb[3];
        __syncthreads();

        // ---- prefetch next tile (overlaps MMA below) ----
        if (t + 1 < NTILES) {
            const float* hp = Hbase + (t + 1) * BK;
            #pragma unroll
            for (int j = 0; j < 8; j++)
                pf[j] = *(const float4*)(hp + (size_t)j * 16 * HIDDEN);
            pb[0] = g_Bhi4[(t + 1) * 512 + tid];
            pb[1] = g_Bhi4[(t + 1) * 512 + 256 + tid];
            pb[2] = g_Blo4[(t + 1) * 512 + tid];
            pb[3] = g_Blo4[(t + 1) * 512 + 256 + tid];
        }

        // ---- MMA phase over buf ----
        #pragma unroll
        for (int s = 0; s < 4; s++) {
            uint32_t ah[2][4], al[2][4], bh[2][4], bl[2][4];
            const uint32_t kb = (uint32_t)(s * 32 + (lane >> 4) * 16);
            #pragma unroll
            for (int mi = 0; mi < 2; mi++) {
                uint32_t off = SWZ128((uint32_t)((wm * 32 + mi * 16 + (lane & 15)) * 128) + kb);
                LDMX4(ah[mi], sb + A_HI(buf) + off);
                LDMX4(al[mi], sb + A_LO(buf) + off);
            }
            #pragma unroll
            for (int g = 0; g < 2; g++) {
                uint32_t off = SWZ128((uint32_t)((wn * 32 + g * 16 + (lane & 15)) * 128) + kb);
                LDMX4(bh[g], sb + B_HI(buf) + off);
                LDMX4(bl[g], sb + B_LO(buf) + off);
            }
            #pragma unroll
            for (int mi = 0; mi < 2; mi++)
                #pragma unroll
                for (int ni = 0; ni < 4; ni++) {
                    const int g = ni >> 1, h = ni & 1;
                    MMA16816(acc[mi][ni], ah[mi], bh[g][h], bh[g][h + 2]);
                    MMA16816(acc[mi][ni], ah[mi], bl[g][h], bl[g][h + 2]);
                    MMA16816(acc[mi][ni], al[mi], bh[g][h], bh[g][h + 2]);
                }
        }
        __syncthreads();
    }

    // ---- LN stats: 16 threads (same tid>>4 group) share each row ----
    #pragma unroll
    for (int o = 1; o < 16; o <<= 1) {
        #pragma unroll
        for (int j = 0; j < 8; j++) {
            psum[j] += __shfl_xor_sync(0xffffffffu, psum[j], o);
            psq[j]  += __shfl_xor_sync(0xffffffffu, psq[j], o);
        }
    }
    if ((tid & 15) == 0) {
        #pragma unroll
        for (int j = 0; j < 8; j++) {
            int row = j * 16 + lrow;
            float mu  = psum[j] * (1.f / HIDDEN);
            float var = psq[j] * (1.f / HIDDEN) - mu * mu;
            ((float*)(dsm + O_MU))[row] = mu;
            ((float*)(dsm + O_RS))[row] = rsqrtf(var + 1e-5f);
        }
    }
    __syncthreads();

    // ---- epilogue: LN-correct + SiLU -> z buffer (reuses A region, stride 68) --
    {
        float* zb = (float*)dsm;   // [128][68]
        const float* muA = (const float*)(dsm + O_MU);
        const float* rsA = (const float*)(dsm + O_RS);
        const float* sA  = (const float*)(dsm + O_S);
        const float* tA  = (const float*)(dsm + O_T);
        #pragma unroll
        for (int mi = 0; mi < 2; mi++) {
            int r0 = wm * 32 + mi * 16 + (lane >> 2);
            float mu0 = muA[r0], rs0 = rsA[r0];
            float mu1 = muA[r0 + 8], rs1 = rsA[r0 + 8];
            #pragma unroll
            for (int ni = 0; ni < 4; ni++) {
                int c0 = wn * 32 + ni * 8 + (lane & 3) * 2;
                float s0 = sA[c0], s1 = sA[c0 + 1];
                float t0 = tA[c0], t1 = tA[c0 + 1];
                float p00 = rs0 * (acc[mi][ni][0] - mu0 * s0) + t0;
                float p01 = rs0 * (acc[mi][ni][1] - mu0 * s1) + t1;
                float p10 = rs1 * (acc[mi][ni][2] - mu1 * s0) + t0;
                float p11 = rs1 * (acc[mi][ni][3] - mu1 * s1) + t1;
                float z00 = p00 / (1.f + __expf(-p00));
                float z01 = p01 / (1.f + __expf(-p01));
                float z10 = p10 / (1.f + __expf(-p10));
                float z11 = p11 / (1.f + __expf(-p11));
                *(float2*)&zb[r0 * ZSTRIDE + c0]       = make_float2(z00, z01);
                *(float2*)&zb[(r0 + 8) * ZSTRIDE + c0] = make_float2(z10, z11);
            }
        }
    }
    __syncthreads();

    // ---- router GEMM + top-2 softmax: one thread per token ----
    if (tid < BM) {
        const float* zr = (const float*)dsm + tid * ZSTRIDE;
        const float* wT = (const float*)(dsm + O_WUPT);
        float lg[8] = {0.f, 0.f, 0.f, 0.f, 0.f, 0.f, 0.f, 0.f};
        #pragma unroll
        for (int d4 = 0; d4 < 16; d4++) {
            float4 zv = *(const float4*)(zr + d4 * 4);
            float zz[4] = {zv.x, zv.y, zv.z, zv.w};
            #pragma unroll
            for (int u = 0; u < 4; u++) {
                int d = d4 * 4 + u;
                float4 wa = *(const float4*)&wT[d * 8];
                float4 wb = *(const float4*)&wT[d * 8 + 4];
                lg[0] = fmaf(zz[u], wa.x, lg[0]); lg[1] = fmaf(zz[u], wa.y, lg[1]);
                lg[2] = fmaf(zz[u], wa.z, lg[2]); lg[3] = fmaf(zz[u], wa.w, lg[3]);
                lg[4] = fmaf(zz[u], wb.x, lg[4]); lg[5] = fmaf(zz[u], wb.y, lg[5]);
                lg[6] = fmaf(zz[u], wb.z, lg[6]); lg[7] = fmaf(zz[u], wb.w, lg[7]);
            }
        }
        int i1 = 0; float m1 = lg[0];
        #pragma unroll
        for (int e = 1; e < 8; e++) if (lg[e] > m1) { m1 = lg[e]; i1 = e; }
        int i2 = -1; float m2 = -3.4e38f;
        #pragma unroll
        for (int e = 0; e < 8; e++) if (e != i1 && lg[e] > m2) { m2 = lg[e]; i2 = e; }
        float p1 = 1.f / (1.f + __expf(m2 - m1));
        float p2 = 1.f - p1;
        float o[8];
        #pragma unroll
        for (int e = 0; e < 8; e++) o[e] = (e == i1) ? p1 : (e == i2) ? p2 : 0.f;
        float* op = out + ((size_t)blockIdx.x * BM + tid) * NEXP;
        *(float4*)op       = make_float4(o[0], o[1], o[2], o[3]);
        *(float4*)(op + 4) = make_float4(o[4], o[5], o[6], o[7]);
    }
}

// ---------------- launch --------------------------------------------------------
extern "C" void kernel_launch(void* const* d_in, const int* in_sizes, int n_in,
                              void* d_out, int out_size)
{
    (void)in_sizes; (void)n_in; (void)out_size;
    const float* hs     = (const float*)d_in[0];
    const float* w_down = (const float*)d_in[1];
    const float* w_up   = (const float*)d_in[2];
    const float* gamma  = (const float*)d_in[3];
    const float* beta   = (const float*)d_in[4];
    float* out = (float*)d_out;

    static int attr_done = 0;
    if (!attr_done) {
        cudaFuncSetAttribute(router_kernel, cudaFuncAttributeMaxDynamicSharedMemorySize, SMEM_TOTAL);
        attr_done = 1;
    }
    prep_kernel<<<BOT, 256>>>(w_down, gamma, beta);
    router_kernel<<<NTOK / BM, THREADS, SMEM_TOTAL>>>(hs, w_up, out);
}

// round 4
// speedup vs baseline: 2.7920x; 1.2000x over previous
#include <cuda_runtime.h>
#include <cuda_bf16.h>
#include <math.h>
#include <stdint.h>

#define HIDDEN 2048
#define BOT    64
#define NEXP   8
#define NTOK   16384

#define BM       64
#define BK       64
#define NTILES   (HIDDEN / BK)       // 32
#define THREADS  256
#define NBLK     (NTOK / BM)         // 256

// ---------------- dynamic smem layout (byte offsets) ---------------------------
#define A_HI(b)   ((b) * 8192)                // 2 x 8KB (64 rows x 128B bf16)
#define A_LO(b)   (16384 + (b) * 8192)
#define B_HI(b)   (32768 + (b) * 8192)        // 2 x 8KB (64 rows x 128B bf16)
#define B_LO(b)   (49152 + (b) * 8192)
#define O_MU      65536                       // 64 f32
#define O_RS      65792
#define O_S       66048
#define O_T       66304
#define O_WUP     66560                       // 2KB raw w_up [8][64]
#define O_LG      68608                       // 2KB logits [64][8]
#define SMEM_TOTAL 70656
#define ZSTRIDE   68

#define SWZ128(off) ((off) ^ (((off) >> 3) & 0x70))

// ---------------- device scratch (no allocations allowed) ----------------------
__device__ uint4 g_Bhi4[NTILES * 512];   // pre-swizzled bf16 hi tiles [n][k]
__device__ uint4 g_Blo4[NTILES * 512];   // lo tiles
__device__ float g_s[BOT];
__device__ float g_t[BOT];

// ---------------- PTX helpers ---------------------------------------------------
__device__ __forceinline__ uint32_t smem_u32(const void* p) {
    uint32_t a;
    asm("{ .reg .u64 t; cvta.to.shared.u64 t, %1; cvt.u32.u64 %0, t; }" : "=r"(a) : "l"(p));
    return a;
}
__device__ __forceinline__ void cpa16(uint32_t dst, const void* src) {
    asm volatile("cp.async.cg.shared.global [%0], [%1], 16;" :: "r"(dst), "l"(src));
}
#define CP_COMMIT() asm volatile("cp.async.commit_group;" ::: "memory")
#define CP_WAIT0()  asm volatile("cp.async.wait_group 0;" ::: "memory")

#define LDMX4(r, a) \
    asm volatile("ldmatrix.sync.aligned.m8n8.x4.shared.b16 {%0,%1,%2,%3}, [%4];" \
        : "=r"((r)[0]), "=r"((r)[1]), "=r"((r)[2]), "=r"((r)[3]) : "r"(a))

#define MMA16816(d, a, b0, b1) \
    asm volatile("mma.sync.aligned.m16n8k16.row.col.f32.bf16.bf16.f32 " \
        "{%0,%1,%2,%3}, {%4,%5,%6,%7}, {%8,%9}, {%0,%1,%2,%3};" \
        : "+f"((d)[0]), "+f"((d)[1]), "+f"((d)[2]), "+f"((d)[3]) \
        : "r"((a)[0]), "r"((a)[1]), "r"((a)[2]), "r"((a)[3]), "r"(b0), "r"(b1))

// ---------------- prep: split G = gamma*W into bf16 hi/lo, pre-swizzled ---------
__global__ void prep_kernel(const float* __restrict__ w_down,
                            const float* __restrict__ gamma,
                            const float* __restrict__ beta)
{
    __shared__ float red_s[8], red_t[8];
    const int n   = blockIdx.x;           // 0..63
    const int tid = threadIdx.x;          // 256
    const int k0  = tid * 8;

    float w[8], gv[8], bv[8];
    *(float4*)&w[0]  = *(const float4*)(w_down + n * HIDDEN + k0);
    *(float4*)&w[4]  = *(const float4*)(w_down + n * HIDDEN + k0 + 4);
    *(float4*)&gv[0] = *(const float4*)(gamma + k0);
    *(float4*)&gv[4] = *(const float4*)(gamma + k0 + 4);
    *(float4*)&bv[0] = *(const float4*)(beta + k0);
    *(float4*)&bv[4] = *(const float4*)(beta + k0 + 4);

    float ps = 0.f, pt = 0.f;
    uint32_t hih[4], loh[4];
    #pragma unroll
    for (int p = 0; p < 4; p++) {
        float g0 = gv[2*p] * w[2*p];
        float g1 = gv[2*p+1] * w[2*p+1];
        ps += g0 + g1;
        pt = fmaf(bv[2*p], w[2*p], pt);
        pt = fmaf(bv[2*p+1], w[2*p+1], pt);
        __nv_bfloat162 h = __floats2bfloat162_rn(g0, g1);
        float r0 = g0 - __bfloat162float(h.x);
        float r1 = g1 - __bfloat162float(h.y);
        __nv_bfloat162 l = __floats2bfloat162_rn(r0, r1);
        hih[p] = *(uint32_t*)&h;
        loh[p] = *(uint32_t*)&l;
    }
    const int tile = k0 >> 6, kk = k0 & 63;
    uint32_t off = (uint32_t)(n * 128 + kk * 2);     // 16B-aligned
    uint32_t sw  = SWZ128(off);
    *(uint4*)((char*)g_Bhi4 + tile * 8192 + sw) = make_uint4(hih[0], hih[1], hih[2], hih[3]);
    *(uint4*)((char*)g_Blo4 + tile * 8192 + sw) = make_uint4(loh[0], loh[1], loh[2], loh[3]);

    #pragma unroll
    for (int o = 16; o > 0; o >>= 1) {
        ps += __shfl_xor_sync(0xffffffffu, ps, o);
        pt += __shfl_xor_sync(0xffffffffu, pt, o);
    }
    int wi = tid >> 5, lane = tid & 31;
    if (lane == 0) { red_s[wi] = ps; red_t[wi] = pt; }
    __syncthreads();
    if (tid == 0) {
        float ss = 0.f, tt = 0.f;
        #pragma unroll
        for (int i = 0; i < 8; i++) { ss += red_s[i]; tt += red_t[i]; }
        g_s[n] = ss; g_t[n] = tt;
    }
}

// ---------------- main fused HMMA kernel ----------------------------------------
extern __shared__ char dsm[];

__global__ __launch_bounds__(THREADS, 2)
void router_kernel(const float* __restrict__ H,      // [16384][2048]
                   const float* __restrict__ w_up,   // [8][64]
                   float* __restrict__ out)          // [16384][8]
{
    const uint32_t sb  = smem_u32(dsm);
    const int tid  = threadIdx.x;
    const int wid  = tid >> 5;
    const int lane = tid & 31;
    const int wm   = wid & 1;             // rows wm*32..+32
    const int wn   = wid >> 1;            // cols wn*16..+16

    // small tables
    ((float*)(dsm + O_WUP))[tid]       = w_up[tid];
    ((float*)(dsm + O_WUP))[tid + 256] = w_up[tid + 256];
    if (tid < BOT) {
        ((float*)(dsm + O_S))[tid] = g_s[tid];
        ((float*)(dsm + O_T))[tid] = g_t[tid];
    }

    // A geometry: 4 float4/thread/tile; rows lrow+16j, k quad (tid&15)
    const int lrow = tid >> 4;
    const float* Hbase = H + ((size_t)blockIdx.x * BM + lrow) * HIDDEN + (tid & 15) * 4;
    const uint32_t sts_sw = SWZ128((uint32_t)(lrow * 128 + (tid & 15) * 8));

    float acc[2][2][4];
    #pragma unroll
    for (int mi = 0; mi < 2; mi++)
        #pragma unroll
        for (int ni = 0; ni < 2; ni++)
            #pragma unroll
            for (int r = 0; r < 4; r++) acc[mi][ni][r] = 0.f;

    float psum[4] = {0.f, 0.f, 0.f, 0.f};
    float psq[4]  = {0.f, 0.f, 0.f, 0.f};
    float4 pf[4];

    // prologue: B0 via cp.async, A0 into regs
    cpa16(sb + B_HI(0) + tid * 16,         &g_Bhi4[tid]);
    cpa16(sb + B_HI(0) + (tid + 256) * 16, &g_Bhi4[tid + 256]);
    cpa16(sb + B_LO(0) + tid * 16,         &g_Blo4[tid]);
    cpa16(sb + B_LO(0) + (tid + 256) * 16, &g_Blo4[tid + 256]);
    CP_COMMIT();
    #pragma unroll
    for (int j = 0; j < 4; j++)
        pf[j] = *(const float4*)(Hbase + (size_t)j * 16 * HIDDEN);

    #pragma unroll 1
    for (int t = 0; t < NTILES; t++) {
        const int buf = t & 1;
        // ---- convert A_t regs -> smem ----
        #pragma unroll
        for (int j = 0; j < 4; j++) {
            float4 v = pf[j];
            psum[j] += (v.x + v.y) + (v.z + v.w);
            psq[j]  = fmaf(v.x, v.x, psq[j]); psq[j] = fmaf(v.y, v.y, psq[j]);
            psq[j]  = fmaf(v.z, v.z, psq[j]); psq[j] = fmaf(v.w, v.w, psq[j]);
            __nv_bfloat162 h01 = __floats2bfloat162_rn(v.x, v.y);
            __nv_bfloat162 h23 = __floats2bfloat162_rn(v.z, v.w);
            float rx = v.x - __bfloat162float(h01.x);
            float ry = v.y - __bfloat162float(h01.y);
            float rz = v.z - __bfloat162float(h23.x);
            float rw = v.w - __bfloat162float(h23.y);
            __nv_bfloat162 l01 = __floats2bfloat162_rn(rx, ry);
            __nv_bfloat162 l23 = __floats2bfloat162_rn(rz, rw);
            uint32_t sw = sts_sw + (uint32_t)(j * 2048);
            *(uint2*)(dsm + A_HI(buf) + sw) = make_uint2(*(uint32_t*)&h01, *(uint32_t*)&h23);
            *(uint2*)(dsm + A_LO(buf) + sw) = make_uint2(*(uint32_t*)&l01, *(uint32_t*)&l23);
        }
        // ---- prefetch A_{t+1} (consumed next iter) ----
        if (t + 1 < NTILES) {
            const float* hp = Hbase + (t + 1) * BK;
            #pragma unroll
            for (int j = 0; j < 4; j++)
                pf[j] = *(const float4*)(hp + (size_t)j * 16 * HIDDEN);
        }
        CP_WAIT0();                 // B_t landed
        __syncthreads();            // A_t visible; MMA_{t-1} fully done
        // ---- issue B_{t+1} (safe: post-barrier) ----
        if (t + 1 < NTILES) {
            const uint4* srcH = g_Bhi4 + (t + 1) * 512;
            const uint4* srcL = g_Blo4 + (t + 1) * 512;
            const int nb = buf ^ 1;
            cpa16(sb + B_HI(nb) + tid * 16,         srcH + tid);
            cpa16(sb + B_HI(nb) + (tid + 256) * 16, srcH + tid + 256);
            cpa16(sb + B_LO(nb) + tid * 16,         srcL + tid);
            cpa16(sb + B_LO(nb) + (tid + 256) * 16, srcL + tid + 256);
            CP_COMMIT();
        }
        // ---- MMA over buf ----
        #pragma unroll
        for (int s = 0; s < 4; s++) {
            uint32_t ah[2][4], al[2][4], bh[4], bl[4];
            const uint32_t kb = (uint32_t)(s * 32 + (lane >> 4) * 16);
            #pragma unroll
            for (int mi = 0; mi < 2; mi++) {
                uint32_t off = SWZ128((uint32_t)((wm * 32 + mi * 16 + (lane & 15)) * 128) + kb);
                LDMX4(ah[mi], sb + A_HI(buf) + off);
                LDMX4(al[mi], sb + A_LO(buf) + off);
            }
            {
                uint32_t off = SWZ128((uint32_t)((wn * 16 + (lane & 15)) * 128) + kb);
                LDMX4(bh, sb + B_HI(buf) + off);
                LDMX4(bl, sb + B_LO(buf) + off);
            }
            #pragma unroll
            for (int mi = 0; mi < 2; mi++)
                #pragma unroll
                for (int ni = 0; ni < 2; ni++) {
                    MMA16816(acc[mi][ni], ah[mi], bh[ni], bh[ni + 2]);
                    MMA16816(acc[mi][ni], ah[mi], bl[ni], bl[ni + 2]);
                    MMA16816(acc[mi][ni], al[mi], bh[ni], bh[ni + 2]);
                }
        }
    }
    __syncthreads();    // all MMA done; A region reusable as z-buffer

    // ---- LN stats: groups of 16 consecutive lanes share a row ----
    #pragma unroll
    for (int o = 1; o < 16; o <<= 1) {
        #pragma unroll
        for (int j = 0; j < 4; j++) {
            psum[j] += __shfl_xor_sync(0xffffffffu, psum[j], o);
            psq[j]  += __shfl_xor_sync(0xffffffffu, psq[j], o);
        }
    }
    if ((tid & 15) == 0) {
        #pragma unroll
        for (int j = 0; j < 4; j++) {
            int row = j * 16 + lrow;
            float mu  = psum[j] * (1.f / HIDDEN);
            float var = psq[j] * (1.f / HIDDEN) - mu * mu;
            ((float*)(dsm + O_MU))[row] = mu;
            ((float*)(dsm + O_RS))[row] = rsqrtf(var + 1e-5f);
        }
    }
    __syncthreads();

    // ---- epilogue: LN-correct + SiLU -> z buffer ----
    {
        float* zb = (float*)dsm;
        const float* muA = (const float*)(dsm + O_MU);
        const float* rsA = (const float*)(dsm + O_RS);
        const float* sA  = (const float*)(dsm + O_S);
        const float* tA  = (const float*)(dsm + O_T);
        #pragma unroll
        for (int mi = 0; mi < 2; mi++) {
            int r0 = wm * 32 + mi * 16 + (lane >> 2);
            float mu0 = muA[r0], rs0 = rsA[r0];
            float mu1 = muA[r0 + 8], rs1 = rsA[r0 + 8];
            #pragma unroll
            for (int ni = 0; ni < 2; ni++) {
                int c0 = wn * 16 + ni * 8 + (lane & 3) * 2;
                float s0 = sA[c0], s1 = sA[c0 + 1];
                float t0 = tA[c0], t1 = tA[c0 + 1];
                float p00 = rs0 * (acc[mi][ni][0] - mu0 * s0) + t0;
                float p01 = rs0 * (acc[mi][ni][1] - mu0 * s1) + t1;
                float p10 = rs1 * (acc[mi][ni][2] - mu1 * s0) + t0;
                float p11 = rs1 * (acc[mi][ni][3] - mu1 * s1) + t1;
                float z00 = p00 / (1.f + __expf(-p00));
                float z01 = p01 / (1.f + __expf(-p01));
                float z10 = p10 / (1.f + __expf(-p10));
                float z11 = p11 / (1.f + __expf(-p11));
                *(float2*)&zb[r0 * ZSTRIDE + c0]       = make_float2(z00, z01);
                *(float2*)&zb[(r0 + 8) * ZSTRIDE + c0] = make_float2(z10, z11);
            }
        }
    }
    __syncthreads();

    // ---- router GEMM: thread = (token m, expert pair eg) ----
    {
        const int m = tid & 63, eg = tid >> 6;
        const float* zr = (const float*)dsm + m * ZSTRIDE;
        const float* w0 = (const float*)(dsm + O_WUP) + eg * 128;
        const float* w1 = w0 + 64;
        float l0 = 0.f, l1 = 0.f;
        #pragma unroll
        for (int d4 = 0; d4 < 16; d4++) {
            float4 zv = ((const float4*)zr)[d4];
            float4 wa = ((const float4*)w0)[d4];
            float4 wb = ((const float4*)w1)[d4];
            l0 = fmaf(zv.x, wa.x, l0); l0 = fmaf(zv.y, wa.y, l0);
            l0 = fmaf(zv.z, wa.z, l0); l0 = fmaf(zv.w, wa.w, l0);
            l1 = fmaf(zv.x, wb.x, l1); l1 = fmaf(zv.y, wb.y, l1);
            l1 = fmaf(zv.z, wb.z, l1); l1 = fmaf(zv.w, wb.w, l1);
        }
        ((float*)(dsm + O_LG))[m * 8 + eg * 2]     = l0;
        ((float*)(dsm + O_LG))[m * 8 + eg * 2 + 1] = l1;
    }
    __syncthreads();

    // ---- top-2 softmax (first-index tie-break matches jax.lax.top_k) ----
    if (tid < BM) {
        const float* lp = (const float*)(dsm + O_LG) + tid * 8;
        float lg[8];
        #pragma unroll
        for (int e = 0; e < 8; e++) lg[e] = lp[e];
        int i1 = 0; float m1 = lg[0];
        #pragma unroll
        for (int e = 1; e < 8; e++) if (lg[e] > m1) { m1 = lg[e]; i1 = e; }
        int i2 = -1; float m2 = -3.4e38f;
        #pragma unroll
        for (int e = 0; e < 8; e++) if (e != i1 && lg[e] > m2) { m2 = lg[e]; i2 = e; }
        float p1 = 1.f / (1.f + __expf(m2 - m1));
        float p2 = 1.f - p1;
        float o[8];
        #pragma unroll
        for (int e = 0; e < 8; e++) o[e] = (e == i1) ? p1 : (e == i2) ? p2 : 0.f;
        float* op = out + ((size_t)blockIdx.x * BM + tid) * NEXP;
        *(float4*)op       = make_float4(o[0], o[1], o[2], o[3]);
        *(float4*)(op + 4) = make_float4(o[4], o[5], o[6], o[7]);
    }
}

// ---------------- launch --------------------------------------------------------
extern "C" void kernel_launch(void* const* d_in, const int* in_sizes, int n_in,
                              void* d_out, int out_size)
{
    (void)in_sizes; (void)n_in; (void)out_size;
    const float* hs     = (const float*)d_in[0];
    const float* w_down = (const float*)d_in[1];
    const float* w_up   = (const float*)d_in[2];
    const float* gamma  = (const float*)d_in[3];
    const float* beta   = (const float*)d_in[4];
    float* out = (float*)d_out;

    static int attr_done = 0;
    if (!attr_done) {
        cudaFuncSetAttribute(router_kernel, cudaFuncAttributeMaxDynamicSharedMemorySize, SMEM_TOTAL);
        attr_done = 1;
    }
    prep_kernel<<<BOT, THREADS>>>(w_down, gamma, beta);
    router_kernel<<<NBLK, THREADS, SMEM_TOTAL>>>(hs, w_up, out);
}